// round 2
// baseline (speedup 1.0000x reference)
#include <cuda_runtime.h>
#include <math.h>
#include <stdint.h>

#define MAXT  10000
#define BATCH 4096

#define LOG_GAMMA_F  0.019802627296179712f
#define ALPHA_F     (-1.0050335853501441e-05f)
#define INIT_LOGW_D (-1.3943265262)
#define INIT_LOGP_D (-6.907755278982137)
#define EPSF 1e-12f

__device__ float  g_Rthr[MAXT];    // exp(logit_t) - eps  (death requires ratio < Rthr)
__device__ float  g_u2thr[MAXT];   // conservative lower bound of exp(Rthr*L1): filter on u2
__device__ double g_S[MAXT];       // inclusive prefix sum of r_t
__device__ int    g_tactive;       // # steps where death is possible
__device__ int    g_death[BATCH];  // first death step per batch element (MAXT = never)

// ---------------- scan kernel: scalar sequences (1 block) ----------------
#define NTH   512
#define PER   20            // 512*20 = 10240 >= MAXT
#define NWARP (NTH/32)

__device__ __forceinline__ double blk_scan_excl(double v, int tid, double* wsm) {
    __syncthreads();                 // protect smem reuse across calls
    double x = v;
    #pragma unroll
    for (int o = 1; o < 32; o <<= 1) {
        double y = __shfl_up_sync(0xffffffffu, x, o);
        if ((tid & 31) >= o) x += y;
    }
    int wid = tid >> 5, lid = tid & 31;
    if (lid == 31) wsm[wid] = x;
    __syncthreads();
    if (wid == 0) {
        double w = (lid < NWARP) ? wsm[lid] : 0.0;
        #pragma unroll
        for (int o = 1; o < 32; o <<= 1) {
            double y = __shfl_up_sync(0xffffffffu, w, o);
            if (lid >= o) w += y;
        }
        if (lid < NWARP) wsm[lid] = w;   // inclusive warp prefix
    }
    __syncthreads();
    double base = (wid == 0) ? 0.0 : wsm[wid - 1];
    return base + (x - v);               // exclusive prefix for this thread
}

__global__ void __launch_bounds__(NTH, 1) scan_kernel(const float* __restrict__ acts) {
    __shared__ double wsm[NWARP];
    __shared__ int scnt;
    int tid = threadIdx.x;
    if (tid == 0) scnt = 0;
    int t0 = tid * PER;

    // phase 1: c_t = LOG_GAMMA + log1p(-exp(a_t))   -> logw prefix
    float cincl[PER], fv[PER];
    double run = 0.0;
    #pragma unroll
    for (int i = 0; i < PER; i++) {
        int t = t0 + i;
        float f = 0.0f, c = 0.0f;
        if (t < MAXT) {
            float a = __ldg(acts + t);
            f = __expf(a);
            c = LOG_GAMMA_F + log1pf(-f);
        }
        fv[i] = f;
        run += (double)c;
        cincl[i] = (float)run;           // local inclusive prefix
    }
    double cbase = blk_scan_excl(run, tid, wsm);
    float lwb0 = (float)(INIT_LOGW_D + cbase);

    // phase 2: d_t = ALPHA * f_t * exp(logw_before_t)  -> logp prefix
    // logw grows to ~196 by t=MAXT; clamp exp arg at 30 (only affects t>~1590
    // where logp < -2e5, provably dead) to keep accumulators finite (no inf-inf NaN).
    double run2 = 0.0;
    float dincl[PER];
    #pragma unroll
    for (int i = 0; i < PER; i++) {
        int t = t0 + i;
        float lwb = lwb0 + (i ? cincl[i - 1] : 0.0f);
        float d = 0.0f;
        if (t < MAXT) d = (ALPHA_F * fv[i]) * __expf(fminf(lwb, 30.0f));
        run2 += (double)d;
        dincl[i] = (float)run2;
    }
    double dbase = blk_scan_excl(run2, tid, wsm);

    // phase 3: thresholds + r_t -> S prefix
    double run3 = 0.0;
    float rincl[PER];
    int cnt = 0;
    #pragma unroll
    for (int i = 0; i < PER; i++) {
        int t = t0 + i;
        float r = 0.0f;
        if (t < MAXT) {
            double logp = INIT_LOGP_D + dbase + (i ? (double)dincl[i - 1] : 0.0);
            float p = __expf((float)fmax(logp, -100.0));     // p <= ~1e-3 always
            float Rthr = p * (1.0f + p * (1.0f + p)) - 1e-12f;   // p/(1-p) - eps
            g_Rthr[t]  = Rthr;
            // exp(Rthr*L1) >= 1 - 27.6311*Rthr ; extra margin keeps filter conservative
            g_u2thr[t] = fmaf(-27.66f, Rthr, 0.99999988f);
            cnt += (Rthr > 1e-9f) ? 1 : 0;   // beyond this, death provably impossible
            float lwn = lwb0 + cincl[i];     // new_logw_t
            r = __expf(lwn * 0.001f);
        }
        run3 += (double)r;
        rincl[i] = (float)run3;
    }
    double rbase = blk_scan_excl(run3, tid, wsm);
    #pragma unroll
    for (int i = 0; i < PER; i++) {
        int t = t0 + i;
        if (t < MAXT) g_S[t] = rbase + (double)rincl[i];
    }

    atomicAdd(&scnt, cnt);
    for (int b = tid; b < BATCH; b += NTH) g_death[b] = MAXT;   // reset latch each launch
    __syncthreads();
    if (tid == 0) g_tactive = scnt;
}

// ---------------- detect kernel: first death per batch element ----------------
#define DCHUNK 64
#define DTH    256

__global__ void detect_kernel(const float* __restrict__ u1, const float* __restrict__ u2) {
    int ta = g_tactive;
    int t0 = blockIdx.y * DCHUNK;
    if (t0 >= ta) return;                       // dead region: no memory touched
    int n = min(DCHUNK, ta - t0);

    __shared__ float sR[DCHUNK], sU[DCHUNK];
    if (threadIdx.x < DCHUNK && threadIdx.x < n) {
        int t = t0 + threadIdx.x;
        sR[threadIdx.x] = g_Rthr[t];
        sU[threadIdx.x] = g_u2thr[t];
    }
    __syncthreads();

    int b = blockIdx.x * DTH + threadIdx.x;
    const float* p2 = u2 + (size_t)t0 * BATCH + b;
    const float* p1 = u1 + (size_t)t0 * BATCH + b;
    int ft = 0x7fffffff;
    #pragma unroll 4
    for (int i = 0; i < n; i++) {
        float v2 = __ldg(p2 + (size_t)i * BATCH);
        if (v2 + EPSF > sU[i]) {                // ~3% pass: only then touch u1 / logf
            float v1 = __ldg(p1 + (size_t)i * BATCH);
            float L1 = logf(v1 + EPSF);         // in [-27.632, ~0)
            float y  = sR[i] * L1;              // in (-0.028, 0]
            float ey = 1.0f + y * (1.0f + y * (0.5f + y * (0.16666667f + y * 0.04166667f)));
            if (v2 + EPSF > ey) ft = min(ft, t0 + i);
        }
    }
    if (ft != 0x7fffffff) atomicMin(&g_death[b], ft);
}

// ---------------- finalize: gather S[death-1], mean over batch ----------------
__global__ void final_kernel(float* __restrict__ out) {
    __shared__ double sh[256];
    int tid = threadIdx.x;
    double acc = 0.0;
    for (int b = tid; b < BATCH; b += 256) {
        int t = g_death[b];
        double v;
        if (t >= MAXT)    v = g_S[MAXT - 1];
        else if (t == 0)  v = 0.0;
        else              v = g_S[t - 1];
        acc += v;
    }
    sh[tid] = acc;
    __syncthreads();
    for (int s = 128; s > 0; s >>= 1) {
        if (tid < s) sh[tid] += sh[tid + s];
        __syncthreads();
    }
    if (tid == 0) out[0] = (float)(sh[0] / (double)BATCH);
}

extern "C" void kernel_launch(void* const* d_in, const int* in_sizes, int n_in,
                              void* d_out, int out_size) {
    const float* acts = (const float*)d_in[0];
    const float* u1   = (const float*)d_in[1];
    const float* u2   = (const float*)d_in[2];
    (void)in_sizes; (void)n_in; (void)out_size;

    scan_kernel<<<1, NTH>>>(acts);
    dim3 grid(BATCH / DTH, (MAXT + DCHUNK - 1) / DCHUNK);
    detect_kernel<<<grid, DTH>>>(u1, u2);
    final_kernel<<<1, 256>>>((float*)d_out);
}

// round 3
// speedup vs baseline: 1.9395x; 1.9395x over previous
#include <cuda_runtime.h>
#include <math.h>
#include <stdint.h>

#define MAXT  10000
#define BATCH 4096

#define LOG_GAMMA_F  0.019802627296179712f
#define ALPHA_F     (-1.0050335853501441e-05f)
#define INIT_LOGW_D (-1.3943265262)
#define INIT_LOGP_D (-6.907755278982137)
#define EPSF 1e-12f

#define SBLK 40          // scan blocks (40*256 = 10240 >= MAXT)
#define STH  256

__device__ float  g_csum[SBLK];    // per-block sum of c_t
__device__ float  g_dsum[SBLK];    // per-block sum of d_t
__device__ float  g_rsum[SBLK];    // per-block sum of r_t
__device__ float  g_dexc[MAXT];    // block-local EXCLUSIVE prefix of d
__device__ float  g_rinc[MAXT];    // block-local INCLUSIVE prefix of r
__device__ int    g_death[BATCH];  // first death step (MAXT = never)

// ---------- block-local inclusive scan (256 threads, fp32) ----------
__device__ __forceinline__ float blk_scan_incl(float v, int tid, float* wsm) {
    __syncthreads();                       // protect wsm reuse across calls
    float x = v;
    #pragma unroll
    for (int o = 1; o < 32; o <<= 1) {
        float y = __shfl_up_sync(0xffffffffu, x, o);
        if ((tid & 31) >= o) x += y;
    }
    int wid = tid >> 5, lid = tid & 31;
    if (lid == 31) wsm[wid] = x;
    __syncthreads();
    if (wid == 0) {
        float w = (lid < 8) ? wsm[lid] : 0.0f;
        #pragma unroll
        for (int o = 1; o < 8; o <<= 1) {
            float y = __shfl_up_sync(0xffffffffu, w, o);
            if (lid >= o) w += y;
        }
        if (lid < 8) wsm[lid] = w;
    }
    __syncthreads();
    float base = (wid == 0) ? 0.0f : wsm[wid - 1];
    return base + x;
}

// ---------------- K1: per-block c sums + death reset ----------------
__global__ void scanA_kernel(const float* __restrict__ acts) {
    __shared__ float wsm[8];
    int tid = threadIdx.x, bid = blockIdx.x;
    int t = bid * STH + tid;
    float c = 0.0f;
    if (t < MAXT) {
        float f = __expf(__ldg(acts + t));
        c = LOG_GAMMA_F + log1pf(-f);
    }
    // block reduce
    float x = c;
    #pragma unroll
    for (int o = 16; o > 0; o >>= 1) x += __shfl_down_sync(0xffffffffu, x, o);
    if ((tid & 31) == 0) wsm[tid >> 5] = x;
    __syncthreads();
    if (tid == 0) {
        float s = 0.0f;
        #pragma unroll
        for (int i = 0; i < 8; i++) s += wsm[i];
        g_csum[bid] = s;
    }
    if (bid < BATCH / STH) g_death[bid * STH + tid] = MAXT;
}

// ---------------- K2: d and r elementwise + local prefixes ----------------
__global__ void scanB_kernel(const float* __restrict__ acts) {
    __shared__ float wsm[8];
    __shared__ float scs[SBLK];
    __shared__ double s_cbase;
    int tid = threadIdx.x, bid = blockIdx.x;
    int t = bid * STH + tid;

    if (tid < SBLK) scs[tid] = g_csum[tid];
    float f = 0.0f, c = 0.0f;
    if (t < MAXT) {
        f = __expf(__ldg(acts + t));
        c = LOG_GAMMA_F + log1pf(-f);
    }
    __syncthreads();
    if (tid == 0) {
        double s = 0.0;
        for (int i = 0; i < bid; i++) s += (double)scs[i];
        s_cbase = INIT_LOGW_D + s;
    }
    float cinc = blk_scan_incl(c, tid, wsm);       // includes a leading syncthreads
    float lwb = (float)s_cbase + (cinc - c);       // logw BEFORE step t

    // logw grows to ~196; clamp exp arg (only affects provably-dead region)
    float d = 0.0f, r = 0.0f;
    if (t < MAXT) {
        d = (ALPHA_F * f) * __expf(fminf(lwb, 30.0f));
        r = __expf((lwb + c) * 0.001f);            // exp(new_logw/1000)
    }
    float dinc = blk_scan_incl(d, tid, wsm);
    float rinc = blk_scan_incl(r, tid, wsm);
    if (t < MAXT) {
        g_dexc[t] = dinc - d;
        g_rinc[t] = rinc;
    }
    if (tid == STH - 1) {
        g_dsum[bid] = dinc;
        g_rsum[bid] = rinc;
    }
}

// ---------------- detect: first death per batch element ----------------
#define DCHUNK 64
#define DTH    256

__global__ void detect_kernel(const float* __restrict__ u1, const float* __restrict__ u2) {
    __shared__ float sds[SBLK];
    __shared__ double s_dbase;
    __shared__ float sR[DCHUNK], sU[DCHUNK];
    int tid = threadIdx.x;
    int t0 = blockIdx.y * DCHUNK;

    if (tid < SBLK) sds[tid] = g_dsum[tid];
    __syncthreads();
    if (tid == 0) {
        int B = t0 >> 8;                           // owning scan-block of this chunk
        double s = 0.0;
        for (int i = 0; i < B; i++) s += (double)sds[i];
        s_dbase = INIT_LOGP_D + s;
    }
    __syncthreads();
    if (tid < DCHUNK) {
        int t = t0 + tid;
        float R = 0.0f, U = 2.0f;                  // default: never fires
        if (t < MAXT) {
            float lp = (float)s_dbase + g_dexc[t]; // logp BEFORE step t
            float p = __expf(fmaxf(lp, -87.0f));
            R = p * (1.0f + p * (1.0f + p)) - 1e-12f;   // p/(1-p) - eps
            // exp(R*L1) >= 1 - 27.6311*R ; margin keeps the filter conservative
            U = fmaf(-27.66f, R, 0.99999988f);
        }
        sR[tid] = R; sU[tid] = U;
    }
    __syncthreads();
    // logp monotone decreasing -> R monotone decreasing: if the chunk's first
    // step can't fire even with extreme noise, neither can anything later in it.
    if (sR[0] < 1e-9f) return;

    int b = blockIdx.x * DTH + tid;
    const float* p2 = u2 + (size_t)t0 * BATCH + b;
    const float* p1 = u1 + (size_t)t0 * BATCH + b;
    int ft = 0x7fffffff;
    #pragma unroll 8
    for (int i = 0; i < DCHUNK; i++) {
        float v2 = __ldg(p2 + (size_t)i * BATCH);
        if (v2 + EPSF > sU[i]) {                   // ~3% pass: only then touch u1
            float v1 = __ldg(p1 + (size_t)i * BATCH);
            float L1 = logf(v1 + EPSF);            // in [-27.632, ~0)
            float y  = sR[i] * L1;                 // in (-0.028, 0]
            float ey = 1.0f + y * (1.0f + y * (0.5f + y * (0.16666667f + y * 0.04166667f)));
            if (v2 + EPSF > ey) ft = min(ft, t0 + i);
        }
    }
    if (ft != 0x7fffffff) atomicMin(&g_death[b], ft);
}

// ---------------- finalize: gather S[death-1], mean over batch ----------------
__global__ void final_kernel(float* __restrict__ out) {
    __shared__ float srs[SBLK];
    __shared__ double rpre[SBLK];   // exclusive prefix of block r-sums
    __shared__ double sh[256];
    int tid = threadIdx.x;
    if (tid < SBLK) srs[tid] = g_rsum[tid];
    __syncthreads();
    if (tid == 0) {
        double s = 0.0;
        for (int i = 0; i < SBLK; i++) { rpre[i] = s; s += (double)srs[i]; }
    }
    __syncthreads();

    double acc = 0.0;
    for (int b = tid; b < BATCH; b += 256) {
        int t = g_death[b];
        if (t > MAXT) t = MAXT;
        double v = 0.0;
        if (t > 0) {
            int tm = t - 1;
            v = rpre[tm >> 8] + (double)g_rinc[tm];   // S[t-1]
        }
        acc += v;
    }
    sh[tid] = acc;
    __syncthreads();
    for (int s = 128; s > 0; s >>= 1) {
        if (tid < s) sh[tid] += sh[tid + s];
        __syncthreads();
    }
    if (tid == 0) out[0] = (float)(sh[0] / (double)BATCH);
}

extern "C" void kernel_launch(void* const* d_in, const int* in_sizes, int n_in,
                              void* d_out, int out_size) {
    const float* acts = (const float*)d_in[0];
    const float* u1   = (const float*)d_in[1];
    const float* u2   = (const float*)d_in[2];
    (void)in_sizes; (void)n_in; (void)out_size;

    scanA_kernel<<<SBLK, STH>>>(acts);
    scanB_kernel<<<SBLK, STH>>>(acts);
    dim3 grid(BATCH / DTH, (MAXT + DCHUNK - 1) / DCHUNK);
    detect_kernel<<<grid, DTH>>>(u1, u2);
    final_kernel<<<1, 256>>>((float*)d_out);
}

// round 4
// speedup vs baseline: 2.4641x; 1.2705x over previous
#include <cuda_runtime.h>
#include <math.h>
#include <stdint.h>

#define MAXT  10000
#define BATCH 4096

#define LOG_GAMMA_F  0.019802627296179712f
#define ALPHA_F     (-1.0050335853501441e-05f)
#define INIT_LOGW_D (-1.3943265262)
#define INIT_LOGP_D (-6.907755278982137)
#define EPSF 1e-12f

#define SBLK 40          // scan blocks (40*256 = 10240 >= MAXT)
#define STH  256

__device__ float  g_csum[SBLK];    // per-block sum of c_t
__device__ float  g_dsum[SBLK];    // per-block sum of d_t
__device__ float  g_rsum[SBLK];    // per-block sum of r_t
__device__ float  g_dexc[MAXT];    // block-local EXCLUSIVE prefix of d
__device__ float  g_rinc[MAXT];    // block-local INCLUSIVE prefix of r
__device__ int    g_death[BATCH];  // first death step (MAXT = never)
__device__ double g_acc;           // final sum accumulator
__device__ unsigned g_cnt;         // final ticket

// ---------- parallel double-sum of first B entries of a 40-float smem array ----------
// Uses first 64 threads; result valid in *out after the trailing __syncthreads().
__device__ __forceinline__ void par_sum40(const float* vals, int B, double* out,
                                          double* wtmp, int tid) {
    double x = 0.0;
    if (tid < SBLK && tid < B) x = (double)vals[tid];
    if (tid < 64) {
        #pragma unroll
        for (int o = 16; o > 0; o >>= 1) x += __shfl_down_sync(0xffffffffu, x, o);
        if ((tid & 31) == 0) wtmp[tid >> 5] = x;
    }
    __syncthreads();
    if (tid == 0) *out = wtmp[0] + wtmp[1];
    __syncthreads();
}

// ---------- block-local inclusive scan (256 threads, fp32) ----------
__device__ __forceinline__ float blk_scan_incl(float v, int tid, float* wsm) {
    __syncthreads();
    float x = v;
    #pragma unroll
    for (int o = 1; o < 32; o <<= 1) {
        float y = __shfl_up_sync(0xffffffffu, x, o);
        if ((tid & 31) >= o) x += y;
    }
    int wid = tid >> 5, lid = tid & 31;
    if (lid == 31) wsm[wid] = x;
    __syncthreads();
    if (wid == 0) {
        float w = (lid < 8) ? wsm[lid] : 0.0f;
        #pragma unroll
        for (int o = 1; o < 8; o <<= 1) {
            float y = __shfl_up_sync(0xffffffffu, w, o);
            if (lid >= o) w += y;
        }
        if (lid < 8) wsm[lid] = w;
    }
    __syncthreads();
    float base = (wid == 0) ? 0.0f : wsm[wid - 1];
    return base + x;
}

// ---------------- K1: per-block c sums + state reset ----------------
__global__ void scanA_kernel(const float* __restrict__ acts) {
    __shared__ float wsm[8];
    int tid = threadIdx.x, bid = blockIdx.x;
    int t = bid * STH + tid;
    float c = 0.0f;
    if (t < MAXT) {
        float f = __expf(__ldg(acts + t));
        c = LOG_GAMMA_F + log1pf(-f);
    }
    float x = c;
    #pragma unroll
    for (int o = 16; o > 0; o >>= 1) x += __shfl_down_sync(0xffffffffu, x, o);
    if ((tid & 31) == 0) wsm[tid >> 5] = x;
    __syncthreads();
    if (tid == 0) {
        float s = 0.0f;
        #pragma unroll
        for (int i = 0; i < 8; i++) s += wsm[i];
        g_csum[bid] = s;
        if (bid == 0) { g_acc = 0.0; g_cnt = 0u; }
    }
    if (bid < BATCH / STH) g_death[bid * STH + tid] = MAXT;
}

// ---------------- K2: d and r elementwise + local prefixes ----------------
__global__ void scanB_kernel(const float* __restrict__ acts) {
    __shared__ float wsm[8];
    __shared__ float scs[SBLK];
    __shared__ double wtmp[2];
    __shared__ double s_cbase;
    int tid = threadIdx.x, bid = blockIdx.x;
    int t = bid * STH + tid;

    if (tid < SBLK) scs[tid] = g_csum[tid];
    float f = 0.0f, c = 0.0f;
    if (t < MAXT) {
        f = __expf(__ldg(acts + t));
        c = LOG_GAMMA_F + log1pf(-f);
    }
    __syncthreads();
    par_sum40(scs, bid, &s_cbase, wtmp, tid);

    float cinc = blk_scan_incl(c, tid, wsm);
    float lwb = (float)(INIT_LOGW_D + s_cbase) + (cinc - c);   // logw BEFORE step t

    // logw grows to ~196; clamp exp arg (only affects provably-dead region)
    float d = 0.0f, r = 0.0f;
    if (t < MAXT) {
        d = (ALPHA_F * f) * __expf(fminf(lwb, 30.0f));
        r = __expf((lwb + c) * 0.001f);            // exp(new_logw/1000)
    }
    float dinc = blk_scan_incl(d, tid, wsm);
    float rinc = blk_scan_incl(r, tid, wsm);
    if (t < MAXT) {
        g_dexc[t] = dinc - d;
        g_rinc[t] = rinc;
    }
    if (tid == STH - 1) {
        g_dsum[bid] = dinc;
        g_rsum[bid] = rinc;
    }
}

// ---------------- detect: first death per batch element ----------------
#define DCHUNK 64
#define DTH    256

__global__ void detect_kernel(const float* __restrict__ u1, const float* __restrict__ u2) {
    __shared__ float sds[SBLK];
    __shared__ double wtmp[2];
    __shared__ double s_dbase;
    __shared__ float sR[DCHUNK], sU[DCHUNK];
    int tid = threadIdx.x;
    int t0 = blockIdx.y * DCHUNK;

    if (tid < SBLK) sds[tid] = g_dsum[tid];
    __syncthreads();
    par_sum40(sds, t0 >> 8, &s_dbase, wtmp, tid);   // cross-block d prefix for chunk base

    if (tid < DCHUNK) {
        int t = t0 + tid;
        float R = 0.0f, U = 2.0f;                  // default: never fires
        if (t < MAXT) {
            float lp = (float)(INIT_LOGP_D + s_dbase) + g_dexc[t];  // logp BEFORE step t
            float p = __expf(fmaxf(lp, -87.0f));
            R = p * (1.0f + p * (1.0f + p)) - 1e-12f;   // p/(1-p) - eps
            // exp(R*L1) >= 1 - 27.6311*R ; margin keeps the filter conservative
            U = fmaf(-27.66f, R, 0.99999988f);
        }
        sR[tid] = R; sU[tid] = U;
    }
    __syncthreads();
    // logp monotone decreasing: if the chunk's first step can't fire even with
    // maximal noise, nothing later in it (or after it) can for this chunk.
    if (sR[0] < 1e-9f) return;

    int b = blockIdx.x * DTH + tid;
    const float* p2 = u2 + (size_t)t0 * BATCH + b;
    const float* p1 = u1 + (size_t)t0 * BATCH + b;
    int ft = 0x7fffffff;
    #pragma unroll 8
    for (int i = 0; i < DCHUNK; i++) {
        float v2 = __ldg(p2 + (size_t)i * BATCH);
        if (v2 + EPSF > sU[i]) {                   // ~3% pass: only then touch u1
            float v1 = __ldg(p1 + (size_t)i * BATCH);
            float L1 = logf(v1 + EPSF);            // in [-27.632, ~0)
            float y  = sR[i] * L1;                 // in (-0.028, 0]
            float ey = 1.0f + y * (1.0f + y * (0.5f + y * (0.16666667f + y * 0.04166667f)));
            if (v2 + EPSF > ey) ft = min(ft, t0 + i);
        }
    }
    if (ft != 0x7fffffff) atomicMin(&g_death[b], ft);
}

// ---------------- finalize: gather S[death-1], mean (16 blocks, fused writeout) ----------------
#define FBLK 16
__global__ void final_kernel(float* __restrict__ out) {
    __shared__ float srs[SBLK];
    __shared__ double rpre[SBLK];   // exclusive prefix of block r-sums
    __shared__ double sh[8];
    int tid = threadIdx.x;
    if (tid < SBLK) srs[tid] = g_rsum[tid];
    __syncthreads();
    // 64-thread exclusive double scan over 40 block sums
    if (tid < 64) {
        double x = (tid < SBLK) ? (double)srs[tid] : 0.0;
        double orig = x;
        #pragma unroll
        for (int o = 1; o < 32; o <<= 1) {
            double y = __shfl_up_sync(0xffffffffu, x, o);
            if ((tid & 31) >= o) x += y;
        }
        if (tid == 31) rpre[SBLK + tid >= SBLK ? 0 : 0] = 0.0;  // no-op placeholder
        __shared__ double w0tot;
        if (tid == 31) w0tot = x;
        __syncwarp();
        __syncthreads();
        double base = (tid >= 32) ? w0tot : 0.0;
        if (tid < SBLK) rpre[tid] = base + (x - orig);
    }
    __syncthreads();

    int b = blockIdx.x * 256 + tid;
    int t = g_death[b];
    if (t > MAXT) t = MAXT;
    double v = 0.0;
    if (t > 0) {
        int tm = t - 1;
        v = rpre[tm >> 8] + (double)g_rinc[tm];   // S[t-1]
    }
    // block reduce (256 -> 1)
    #pragma unroll
    for (int o = 16; o > 0; o >>= 1) v += __shfl_down_sync(0xffffffffu, v, o);
    if ((tid & 31) == 0) sh[tid >> 5] = v;
    __syncthreads();
    if (tid == 0) {
        double s = 0.0;
        #pragma unroll
        for (int i = 0; i < 8; i++) s += sh[i];
        atomicAdd(&g_acc, s);
        __threadfence();
        unsigned ticket = atomicAdd(&g_cnt, 1u);
        if (ticket == FBLK - 1) {
            double tot = atomicAdd(&g_acc, 0.0);   // all adds visible (fence+ticket)
            out[0] = (float)(tot / (double)BATCH);
        }
    }
}

extern "C" void kernel_launch(void* const* d_in, const int* in_sizes, int n_in,
                              void* d_out, int out_size) {
    const float* acts = (const float*)d_in[0];
    const float* u1   = (const float*)d_in[1];
    const float* u2   = (const float*)d_in[2];
    (void)in_sizes; (void)n_in; (void)out_size;

    scanA_kernel<<<SBLK, STH>>>(acts);
    scanB_kernel<<<SBLK, STH>>>(acts);
    dim3 grid(BATCH / DTH, (MAXT + DCHUNK - 1) / DCHUNK);
    detect_kernel<<<grid, DTH>>>(u1, u2);
    final_kernel<<<FBLK, 256>>>((float*)d_out);
}